// round 2
// baseline (speedup 1.0000x reference)
#include <cuda_runtime.h>
#include <math.h>

#define SS 512
#define DD 512
#define HH 8
#define HD 64
#define NE 1024

// Scratch (no cudaMalloc allowed)
__device__ float g_Q[SS * DD];
__device__ float g_K[SS * DD];
__device__ float g_V[SS * DD];
__device__ float g_RK[NE * DD];
__device__ float g_RQ[NE * DD];
__device__ float g_QK[HH * SS * SS];
__device__ float g_M2[HH * SS * NE];
__device__ float g_M3[HH * NE * SS];
__device__ float g_CTX[SS * DD];

// ---------------------------------------------------------------------------
// Generic batched GEMM: C[m,n] = sum_k A[m,k] * B[n,k] (+bias[n])
//   A: element (m,k) at A[m*sa_r + k]            (k contiguous)
//   B: element (n,k) at B[n*sb_r + k*sb_c]       (either sb_c==1 or sb_r==1)
//   C: element (m,n) at C[m*sc_r + n]            (n contiguous)
// Tiles: 64x64x16, 256 threads, 4x4 per-thread microtile.
// All M,N multiples of 64; K multiple of 16. blockIdx.z = batch.
// ---------------------------------------------------------------------------
__global__ __launch_bounds__(256) void gemm_tn(
    const float* __restrict__ A, const float* __restrict__ B,
    const float* __restrict__ bias, float* __restrict__ C,
    int K,
    int sa_r, int sb_r, int sb_c, int sc_r,
    long bat_a, long bat_b, long bat_c)
{
    A += (long)blockIdx.z * bat_a;
    B += (long)blockIdx.z * bat_b;
    C += (long)blockIdx.z * bat_c;

    const int m0 = blockIdx.y * 64;
    const int n0 = blockIdx.x * 64;

    __shared__ float As[16][68];
    __shared__ float Bs[16][68];

    const int tid = threadIdx.x;
    const int tx = tid & 15;       // n direction (16)
    const int ty = tid >> 4;       // m direction (16)

    float acc[4][4] = {};

    for (int k0 = 0; k0 < K; k0 += 16) {
        // Load A tile (k contiguous in gmem)
        #pragma unroll
        for (int e = tid; e < 1024; e += 256) {
            int k = e & 15, m = e >> 4;
            As[k][m] = A[(long)(m0 + m) * sa_r + (k0 + k)];
        }
        // Load B tile, choose coalescing-friendly mapping
        if (sb_c == 1) {
            #pragma unroll
            for (int e = tid; e < 1024; e += 256) {
                int k = e & 15, n = e >> 4;
                Bs[k][n] = B[(long)(n0 + n) * sb_r + (k0 + k)];
            }
        } else {
            #pragma unroll
            for (int e = tid; e < 1024; e += 256) {
                int n = e & 63, k = e >> 6;
                Bs[k][n] = B[(long)(n0 + n) * sb_r + (long)(k0 + k) * sb_c];
            }
        }
        __syncthreads();

        #pragma unroll
        for (int k = 0; k < 16; k++) {
            float a[4], b[4];
            #pragma unroll
            for (int i = 0; i < 4; i++) a[i] = As[k][ty * 4 + i];
            #pragma unroll
            for (int j = 0; j < 4; j++) b[j] = Bs[k][tx * 4 + j];
            #pragma unroll
            for (int i = 0; i < 4; i++)
                #pragma unroll
                for (int j = 0; j < 4; j++)
                    acc[i][j] = fmaf(a[i], b[j], acc[i][j]);
        }
        __syncthreads();
    }

    #pragma unroll
    for (int i = 0; i < 4; i++) {
        const int m = m0 + ty * 4 + i;
        #pragma unroll
        for (int j = 0; j < 4; j++) {
            const int n = n0 + tx * 4 + j;
            float v = acc[i][j];
            if (bias) v += bias[n];
            C[(long)m * sc_r + n] = v;
        }
    }
}

// ---------------------------------------------------------------------------
// scores gather + scale + softmax:
//   s[h,i,j] = (QK[h,i,j] + M2[h,i,j-i+512] + M3[h,j-i+512,j]) / 8
//   attn[h,i,j] = softmax_j(s)
// One block per (i, h), 256 threads, 2 columns each.
// ---------------------------------------------------------------------------
__global__ __launch_bounds__(256) void softmax_kernel(
    const float* __restrict__ QK, const float* __restrict__ M2,
    const float* __restrict__ M3, float* __restrict__ attn)
{
    const int i = blockIdx.x;
    const int h = blockIdx.y;
    const int t = threadIdx.x;

    __shared__ float sh[8];
    __shared__ float bcast;

    float s[2];
    #pragma unroll
    for (int u = 0; u < 2; u++) {
        const int j = t + u * 256;
        const int r = j - i + 512;
        s[u] = (QK[(h * SS + i) * SS + j]
              + M2[(h * SS + i) * NE + r]
              + M3[(h * NE + r) * SS + j]) * 0.125f;
    }

    // block max
    float v = fmaxf(s[0], s[1]);
    #pragma unroll
    for (int o = 16; o; o >>= 1) v = fmaxf(v, __shfl_xor_sync(0xffffffffu, v, o));
    if ((t & 31) == 0) sh[t >> 5] = v;
    __syncthreads();
    if (t < 32) {
        float w = (t < 8) ? sh[t] : -INFINITY;
        #pragma unroll
        for (int o = 4; o; o >>= 1) w = fmaxf(w, __shfl_xor_sync(0xffffffffu, w, o));
        if (t == 0) bcast = w;
    }
    __syncthreads();
    const float mx = bcast;

    const float e0 = __expf(s[0] - mx);
    const float e1 = __expf(s[1] - mx);

    // block sum
    v = e0 + e1;
    #pragma unroll
    for (int o = 16; o; o >>= 1) v += __shfl_xor_sync(0xffffffffu, v, o);
    __syncthreads();  // protect sh reuse
    if ((t & 31) == 0) sh[t >> 5] = v;
    __syncthreads();
    if (t < 32) {
        float w = (t < 8) ? sh[t] : 0.f;
        #pragma unroll
        for (int o = 4; o; o >>= 1) w += __shfl_xor_sync(0xffffffffu, w, o);
        if (t == 0) bcast = w;
    }
    __syncthreads();
    const float inv = 1.0f / bcast;

    attn[(h * SS + i) * SS + t]       = e0 * inv;
    attn[(h * SS + i) * SS + t + 256] = e1 * inv;
}

extern "C" void kernel_launch(void* const* d_in, const int* in_sizes, int n_in,
                              void* d_out, int out_size)
{
    const float* hs  = (const float*)d_in[0];
    const float* emb = (const float*)d_in[1];
    const float* wq  = (const float*)d_in[2];
    const float* bq  = (const float*)d_in[3];
    const float* wk  = (const float*)d_in[4];
    const float* bk  = (const float*)d_in[5];
    const float* wv  = (const float*)d_in[6];
    const float* bv  = (const float*)d_in[7];
    const float* wrk = (const float*)d_in[8];
    const float* brk = (const float*)d_in[9];
    const float* wrq = (const float*)d_in[10];
    const float* brq = (const float*)d_in[11];
    const float* wo  = (const float*)d_in[12];
    const float* bo  = (const float*)d_in[13];

    float* out  = (float*)d_out;            // [1,512,512]
    float* attn = out + SS * DD;            // [1,8,512,512]

    float *Q, *K, *V, *RK, *RQ, *QK, *M2, *M3, *CTX;
    cudaGetSymbolAddress((void**)&Q,  g_Q);
    cudaGetSymbolAddress((void**)&K,  g_K);
    cudaGetSymbolAddress((void**)&V,  g_V);
    cudaGetSymbolAddress((void**)&RK, g_RK);
    cudaGetSymbolAddress((void**)&RQ, g_RQ);
    cudaGetSymbolAddress((void**)&QK, g_QK);
    cudaGetSymbolAddress((void**)&M2, g_M2);
    cudaGetSymbolAddress((void**)&M3, g_M3);
    cudaGetSymbolAddress((void**)&CTX, g_CTX);

    const dim3 thr(256);

    // q, k, v projections: [512,512] = hs[512,512] @ W^T + b
    gemm_tn<<<dim3(8, 8, 1), thr>>>(hs, wq, bq, Q, 512, 512, 512, 1, 512, 0, 0, 0);
    gemm_tn<<<dim3(8, 8, 1), thr>>>(hs, wk, bk, K, 512, 512, 512, 1, 512, 0, 0, 0);
    gemm_tn<<<dim3(8, 8, 1), thr>>>(hs, wv, bv, V, 512, 512, 512, 1, 512, 0, 0, 0);

    // relative key/query projections over the 1024 distinct embeddings
    gemm_tn<<<dim3(8, 16, 1), thr>>>(emb, wrk, brk, RK, 512, 512, 512, 1, 512, 0, 0, 0);
    gemm_tn<<<dim3(8, 16, 1), thr>>>(emb, wrq, brq, RQ, 512, 512, 512, 1, 512, 0, 0, 0);

    // QK[h] = Qh @ Kh^T   [512x512x64], batched over heads via +h*64 offsets
    gemm_tn<<<dim3(8, 8, HH), thr>>>(Q, K, nullptr, QK, 64, 512, 512, 1, 512,
                                     64, 64, (long)SS * SS);
    // M2[h,i,r] = Qh @ RKh^T   [512x1024x64]
    gemm_tn<<<dim3(16, 8, HH), thr>>>(Q, RK, nullptr, M2, 64, 512, 512, 1, 1024,
                                      64, 64, (long)SS * NE);
    // M3[h,r,j] = RQh @ Kh^T   [1024x512x64]
    gemm_tn<<<dim3(8, 16, HH), thr>>>(RQ, K, nullptr, M3, 64, 512, 512, 1, 512,
                                      64, 64, (long)NE * SS);

    // gather + scale + softmax -> attn (written directly into d_out)
    softmax_kernel<<<dim3(SS, HH), thr>>>(QK, M2, M3, attn);

    // ctx[h] = attn[h] @ Vh   [512x64x512], B accessed transposed (sb_r=1, sb_c=512)
    gemm_tn<<<dim3(1, 8, HH), thr>>>(attn, V, nullptr, CTX, 512, 512, 1, 512, 512,
                                     (long)SS * SS, 64, 64);

    // output projection
    gemm_tn<<<dim3(8, 8, 1), thr>>>(CTX, wo, bo, out, 512, 512, 512, 1, 512, 0, 0, 0);
}

// round 7
// speedup vs baseline: 1.3848x; 1.3848x over previous
#include <cuda_runtime.h>
#include <math.h>
#include <stdint.h>

#define SS 512
#define DD 512
#define HH 8
#define NE 1024

// Scratch (no cudaMalloc allowed). 16B-aligned for float4 access.
__device__ __align__(16) float g_Q[SS * DD];
__device__ __align__(16) float g_K[SS * DD];
__device__ __align__(16) float g_V[SS * DD];
__device__ __align__(16) float g_RK[NE * DD];
__device__ __align__(16) float g_RQ[NE * DD];
__device__ __align__(16) float g_QK[HH * SS * SS];
__device__ __align__(16) float g_M2[HH * SS * NE];
__device__ __align__(16) float g_M3[HH * NE * SS];
__device__ __align__(16) float g_CTX[SS * DD];

__device__ __forceinline__ uint32_t f2tf32(float x) {
    uint32_t r;
    asm("cvt.rna.tf32.f32 %0, %1;" : "=r"(r) : "f"(x));
    return r;
}

// ---------------------------------------------------------------------------
// Batched tf32 tensor-core GEMM: C[m,n] = sum_k A[m,k]*B[n,k] (+bias[n])
//   A: (m,k) at A[m*sa_r + k]                (k contiguous)
//   B: (n,k) at B[n*sb_r + k*sb_c]           (sb_c==1: k contig; else n contig)
//   C: (m,n) at C[m*sc_r + n]
// Block tile 128x64xK(chunk 32), 256 threads = 8 warps (4m x 2n),
// warp tile 32x32 = 2x4 m16n8k8 mma tiles. M%128==0, N%64==0, K%32==0.
// ---------------------------------------------------------------------------
__global__ __launch_bounds__(256) void gemm_mma(
    const float* __restrict__ A, const float* __restrict__ B,
    const float* __restrict__ bias, float* __restrict__ C,
    int K, int sa_r, int sb_r, int sb_c, int sc_r,
    long bat_a, long bat_b, long bat_c)
{
    A += (long)blockIdx.z * bat_a;
    B += (long)blockIdx.z * bat_b;
    C += (long)blockIdx.z * bat_c;

    const int m0 = blockIdx.y * 128;
    const int n0 = blockIdx.x * 64;

    // Strides chosen so fragment-load banks are conflict-free:
    //   As: bank = (row*36 + k)%32 = (row*4 + k)%32 -> rows 0..7 x k 0..3 distinct
    //   Bs: bank = (k*72 + n)%32  = (k*8 + n)%32   -> k 0..3 x n 0..7 distinct
    __shared__ uint32_t As[128][36];
    __shared__ uint32_t Bs[32][72];

    const int tid  = threadIdx.x;
    const int warp = tid >> 5;
    const int lane = tid & 31;
    const int g    = lane >> 2;   // group id (0..7)
    const int tg   = lane & 3;    // thread-in-group

    const int wm = (warp & 3) * 32;   // warp m base within tile
    const int wn = (warp >> 2) * 32;  // warp n base within tile

    float acc[2][4][4];
    #pragma unroll
    for (int mi = 0; mi < 2; mi++)
        #pragma unroll
        for (int ni = 0; ni < 4; ni++)
            #pragma unroll
            for (int r = 0; r < 4; r++) acc[mi][ni][r] = 0.f;

    for (int k0 = 0; k0 < K; k0 += 32) {
        // ---- load A tile (128x32), float4, convert to tf32 ----
        #pragma unroll
        for (int it = 0; it < 4; it++) {
            int idx = tid + it * 256;      // 1024 float4-slots
            int row = idx >> 3;            // 8 float4 per row
            int c4  = (idx & 7) * 4;
            const float4 v = *(const float4*)(A + (long)(m0 + row) * sa_r + k0 + c4);
            As[row][c4 + 0] = f2tf32(v.x);
            As[row][c4 + 1] = f2tf32(v.y);
            As[row][c4 + 2] = f2tf32(v.z);
            As[row][c4 + 3] = f2tf32(v.w);
        }
        // ---- load B tile into Bs[k][n] (32x64) ----
        if (sb_c == 1) {
            #pragma unroll
            for (int it = 0; it < 2; it++) {
                int idx = tid + it * 256;  // 64 rows x 8 float4
                int n   = idx >> 3;
                int c4  = (idx & 7) * 4;
                const float4 v = *(const float4*)(B + (long)(n0 + n) * sb_r + k0 + c4);
                Bs[c4 + 0][n] = f2tf32(v.x);
                Bs[c4 + 1][n] = f2tf32(v.y);
                Bs[c4 + 2][n] = f2tf32(v.z);
                Bs[c4 + 3][n] = f2tf32(v.w);
            }
        } else {
            #pragma unroll
            for (int it = 0; it < 2; it++) {
                int idx = tid + it * 256;  // 32 k-rows x 16 float4
                int k   = idx >> 4;
                int c4  = (idx & 15) * 4;
                const float4 v = *(const float4*)(B + (long)(k0 + k) * sb_c + n0 + c4);
                Bs[k][c4 + 0] = f2tf32(v.x);
                Bs[k][c4 + 1] = f2tf32(v.y);
                Bs[k][c4 + 2] = f2tf32(v.z);
                Bs[k][c4 + 3] = f2tf32(v.w);
            }
        }
        __syncthreads();

        #pragma unroll
        for (int ks = 0; ks < 4; ks++) {
            const int kk = ks * 8;
            uint32_t a[2][4], b[4][2];
            #pragma unroll
            for (int mi = 0; mi < 2; mi++) {
                const int r0 = wm + mi * 16 + g;
                a[mi][0] = As[r0][kk + tg];
                a[mi][1] = As[r0 + 8][kk + tg];
                a[mi][2] = As[r0][kk + tg + 4];
                a[mi][3] = As[r0 + 8][kk + tg + 4];
            }
            #pragma unroll
            for (int ni = 0; ni < 4; ni++) {
                const int nn = wn + ni * 8 + g;
                b[ni][0] = Bs[kk + tg][nn];
                b[ni][1] = Bs[kk + tg + 4][nn];
            }
            #pragma unroll
            for (int mi = 0; mi < 2; mi++)
                #pragma unroll
                for (int ni = 0; ni < 4; ni++) {
                    asm volatile(
                        "mma.sync.aligned.m16n8k8.row.col.f32.tf32.tf32.f32 "
                        "{%0,%1,%2,%3}, {%4,%5,%6,%7}, {%8,%9}, {%0,%1,%2,%3};\n"
                        : "+f"(acc[mi][ni][0]), "+f"(acc[mi][ni][1]),
                          "+f"(acc[mi][ni][2]), "+f"(acc[mi][ni][3])
                        : "r"(a[mi][0]), "r"(a[mi][1]), "r"(a[mi][2]), "r"(a[mi][3]),
                          "r"(b[ni][0]), "r"(b[ni][1]));
                }
        }
        __syncthreads();
    }

    // ---- epilogue: bias + store (float2 pairs, c-fragment layout) ----
    #pragma unroll
    for (int mi = 0; mi < 2; mi++) {
        #pragma unroll
        for (int ni = 0; ni < 4; ni++) {
            const int row = m0 + wm + mi * 16 + g;
            const int col = n0 + wn + ni * 8 + tg * 2;
            float b0 = bias ? bias[col] : 0.f;
            float b1 = bias ? bias[col + 1] : 0.f;
            float2 v0 = make_float2(acc[mi][ni][0] + b0, acc[mi][ni][1] + b1);
            float2 v1 = make_float2(acc[mi][ni][2] + b0, acc[mi][ni][3] + b1);
            *(float2*)(C + (long)row * sc_r + col)       = v0;
            *(float2*)(C + (long)(row + 8) * sc_r + col) = v1;
        }
    }
}

// ---------------------------------------------------------------------------
// scores gather + scale + softmax (unchanged)
// ---------------------------------------------------------------------------
__global__ __launch_bounds__(256) void softmax_kernel(
    const float* __restrict__ QK, const float* __restrict__ M2,
    const float* __restrict__ M3, float* __restrict__ attn)
{
    const int i = blockIdx.x;
    const int h = blockIdx.y;
    const int t = threadIdx.x;

    __shared__ float sh[8];
    __shared__ float bcast;

    float s[2];
    #pragma unroll
    for (int u = 0; u < 2; u++) {
        const int j = t + u * 256;
        const int r = j - i + 512;
        s[u] = (QK[(h * SS + i) * SS + j]
              + M2[(h * SS + i) * NE + r]
              + M3[(h * NE + r) * SS + j]) * 0.125f;
    }

    float v = fmaxf(s[0], s[1]);
    #pragma unroll
    for (int o = 16; o; o >>= 1) v = fmaxf(v, __shfl_xor_sync(0xffffffffu, v, o));
    if ((t & 31) == 0) sh[t >> 5] = v;
    __syncthreads();
    if (t < 32) {
        float w = (t < 8) ? sh[t] : -INFINITY;
        #pragma unroll
        for (int o = 4; o; o >>= 1) w = fmaxf(w, __shfl_xor_sync(0xffffffffu, w, o));
        if (t == 0) bcast = w;
    }
    __syncthreads();
    const float mx = bcast;

    const float e0 = __expf(s[0] - mx);
    const float e1 = __expf(s[1] - mx);

    v = e0 + e1;
    #pragma unroll
    for (int o = 16; o; o >>= 1) v += __shfl_xor_sync(0xffffffffu, v, o);
    __syncthreads();
    if ((t & 31) == 0) sh[t >> 5] = v;
    __syncthreads();
    if (t < 32) {
        float w = (t < 8) ? sh[t] : 0.f;
        #pragma unroll
        for (int o = 4; o; o >>= 1) w += __shfl_xor_sync(0xffffffffu, w, o);
        if (t == 0) bcast = w;
    }
    __syncthreads();
    const float inv = 1.0f / bcast;

    attn[(h * SS + i) * SS + t]       = e0 * inv;
    attn[(h * SS + i) * SS + t + 256] = e1 * inv;
}

extern "C" void kernel_launch(void* const* d_in, const int* in_sizes, int n_in,
                              void* d_out, int out_size)
{
    const float* hs  = (const float*)d_in[0];
    const float* emb = (const float*)d_in[1];
    const float* wq  = (const float*)d_in[2];
    const float* bq  = (const float*)d_in[3];
    const float* wk  = (const float*)d_in[4];
    const float* bk  = (const float*)d_in[5];
    const float* wv  = (const float*)d_in[6];
    const float* bv  = (const float*)d_in[7];
    const float* wrk = (const float*)d_in[8];
    const float* brk = (const float*)d_in[9];
    const float* wrq = (const float*)d_in[10];
    const float* brq = (const float*)d_in[11];
    const float* wo  = (const float*)d_in[12];
    const float* bo  = (const float*)d_in[13];

    float* out  = (float*)d_out;            // [1,512,512]
    float* attn = out + SS * DD;            // [1,8,512,512]

    float *Q, *K, *V, *RK, *RQ, *QK, *M2, *M3, *CTX;
    cudaGetSymbolAddress((void**)&Q,  g_Q);
    cudaGetSymbolAddress((void**)&K,  g_K);
    cudaGetSymbolAddress((void**)&V,  g_V);
    cudaGetSymbolAddress((void**)&RK, g_RK);
    cudaGetSymbolAddress((void**)&RQ, g_RQ);
    cudaGetSymbolAddress((void**)&QK, g_QK);
    cudaGetSymbolAddress((void**)&M2, g_M2);
    cudaGetSymbolAddress((void**)&M3, g_M3);
    cudaGetSymbolAddress((void**)&CTX, g_CTX);

    const dim3 thr(256);

    // q, k, v projections: [512,512] = hs @ W^T + b
    gemm_mma<<<dim3(8, 4, 1), thr>>>(hs, wq, bq, Q, 512, 512, 512, 1, 512, 0, 0, 0);
    gemm_mma<<<dim3(8, 4, 1), thr>>>(hs, wk, bk, K, 512, 512, 512, 1, 512, 0, 0, 0);
    gemm_mma<<<dim3(8, 4, 1), thr>>>(hs, wv, bv, V, 512, 512, 512, 1, 512, 0, 0, 0);

    // relative projections over 1024 distinct embeddings
    gemm_mma<<<dim3(8, 8, 1), thr>>>(emb, wrk, brk, RK, 512, 512, 512, 1, 512, 0, 0, 0);
    gemm_mma<<<dim3(8, 8, 1), thr>>>(emb, wrq, brq, RQ, 512, 512, 512, 1, 512, 0, 0, 0);

    // QK[h] = Qh @ Kh^T
    gemm_mma<<<dim3(8, 4, HH), thr>>>(Q, K, nullptr, QK, 64, 512, 512, 1, 512,
                                      64, 64, (long)SS * SS);
    // M2[h,i,r] = Qh @ RKh^T
    gemm_mma<<<dim3(16, 4, HH), thr>>>(Q, RK, nullptr, M2, 64, 512, 512, 1, 1024,
                                       64, 64, (long)SS * NE);
    // M3[h,r,j] = RQh @ Kh^T
    gemm_mma<<<dim3(8, 8, HH), thr>>>(RQ, K, nullptr, M3, 64, 512, 512, 1, 512,
                                      64, 64, (long)NE * SS);

    // gather + scale + softmax -> attn (into d_out)
    softmax_kernel<<<dim3(SS, HH), thr>>>(QK, M2, M3, attn);

    // ctx[h] = attn[h] @ Vh (B accessed n-contiguous: sb_r=1, sb_c=512)
    gemm_mma<<<dim3(1, 4, HH), thr>>>(attn, V, nullptr, CTX, 512, 512, 1, 512, 512,
                                      (long)SS * SS, 64, 64);

    // output projection
    gemm_mma<<<dim3(8, 4, 1), thr>>>(CTX, wo, bo, out, 512, 512, 512, 1, 512, 0, 0, 0);
}